// round 7
// baseline (speedup 1.0000x reference)
#include <cuda_runtime.h>

// InfoEnlargeEmbedding: out[b,l,:] = concat(x[b,l,:], x[b,idxs[b,0],:], x[b,idxs[b,1],:])
// B=64, L=1024, D=256, K=2.
// R7: R6 structure with register-pressure fix. Copy path pipelined as two
// 4-row chunks (16 live data regs instead of 32); __launch_bounds__(192, 8)
// to raise resident CTAs/SM and deepen the chip-wide in-flight write queue.

static constexpr int B = 64;
static constexpr int L = 1024;
static constexpr int D4 = 64;               // float4 per source row
static constexpr int K = 2;
static constexpr int OUT4 = D4 * (1 + K);   // 192 float4 per output row
static constexpr int R = 8;                 // rows (bl) per block
static constexpr int H = 4;                 // pipeline chunk (rows)

__global__ void __launch_bounds__(192, 8)
info_enlarge_kernel(const float4* __restrict__ x,
                    const int* __restrict__ idxs,
                    float4* __restrict__ out) {
    const int row0 = blockIdx.x * R;        // base bl; all R rows share b
    const int b    = row0 >> 10;            // / L
    const int c    = threadIdx.x;           // 0..191

    if (c < D4) {
        // Straight copy: two pipelined chunks of 4 independent load->store.
        #pragma unroll
        for (int h = 0; h < R / H; h++) {
            const int rb = row0 + h * H;
            float4 v[H];
            #pragma unroll
            for (int u = 0; u < H; u++)
                v[u] = x[(size_t)(rb + u) * D4 + c];
            #pragma unroll
            for (int u = 0; u < H; u++)
                out[(size_t)(rb + u) * OUT4 + c] = v[u];
        }
    } else {
        // Gather: same source value for all 8 output rows (L2-hit load).
        const int kd = c - D4;
        const int k  = kd >> 6;             // / D4
        const int dd = kd & (D4 - 1);
        const int li = __ldg(idxs + b * K + k);
        const float4 v = __ldg(x + ((size_t)b * L + li) * D4 + dd);
        #pragma unroll
        for (int u = 0; u < R; u++)
            out[(size_t)(row0 + u) * OUT4 + c] = v;
    }
}

extern "C" void kernel_launch(void* const* d_in, const int* in_sizes, int n_in,
                              void* d_out, int out_size) {
    const float4* x  = (const float4*)d_in[0];
    const int* idxs  = (const int*)d_in[1];
    float4* out      = (float4*)d_out;

    info_enlarge_kernel<<<(B * L) / R, 192>>>(x, idxs, out);
}